// round 6
// baseline (speedup 1.0000x reference)
#include <cuda_runtime.h>

// LSTM T=512, B=4096, I=10, H=20. One warp per TWO batch rows; weights
// register-resident (f32x2); fma.rn.f32x2; tanh.approx. 512 CTAs = one wave
// at 4 CTA/SM. R6: x-projection for step t+1 is computed into the (dead)
// accumulators right after the gate-exchange sync, covering gate-LDS latency
// and the phase2 serial chain with FMA work. Phase2 spread over 32 lanes.
// Smem strides chosen == 20 (mod 32) for conflict-free phase2 access.

#define T_STEPS 512
#define BATCH   4096
#define ISZ     10
#define HSZ     20
#define JPAD    24
#define WARPS_PER_CTA 4
#define NB      8                  // 2 rows/warp * 4 warps
#define NTHREADS 128

// per-warp smem floats
#define H_ROW   52                 // row stride within an h buffer (==20 mod 32)
#define HB_BUF  80                 // h buffer stride (2 buffers)
#define H_OFF   0                  // hbuf: 160
#define G_ROW   116                // gate row stride (==20 mod 32)
#define G_OFF   160                // gbuf: 212 -> pad 216
#define X_OFF   (160 + 216)        // xs: 2 bufs * 24 = 48
#define WREG_F  (160 + 216 + 48)   // 424 floats

typedef unsigned long long u64;

__device__ __forceinline__ u64 pack2(float x, float y) {
    u64 r; asm("mov.b64 %0, {%1,%2};" : "=l"(r) : "f"(x), "f"(y)); return r;
}
__device__ __forceinline__ void unpack2(u64 v, float& x, float& y) {
    asm("mov.b64 {%0,%1}, %2;" : "=f"(x), "=f"(y) : "l"(v));
}
__device__ __forceinline__ u64 ffma2(u64 a, u64 b, u64 c) {
    u64 r; asm("fma.rn.f32x2 %0, %1, %2, %3;" : "=l"(r) : "l"(a), "l"(b), "l"(c));
    return r;
}
__device__ __forceinline__ float tanh_fast(float x) {
    float y; asm("tanh.approx.f32 %0, %1;" : "=f"(y) : "f"(x)); return y;
}

// acc = bias + Wih * x (both rows); accumulators are fresh here.
__device__ __forceinline__ void xproj(u64 acc[2][3], const float* xsb,
                                      const u64 (&wih2)[3][5],
                                      const u64 (&bias2)[3]) {
#pragma unroll
    for (int r = 0; r < 2; r++) {
        acc[r][0] = bias2[0]; acc[r][1] = bias2[1]; acc[r][2] = bias2[2];
        const float* xrow = xsb + r * 12;
        const ulonglong2 xa = *reinterpret_cast<const ulonglong2*>(xrow);
        const ulonglong2 xb = *reinterpret_cast<const ulonglong2*>(xrow + 4);
        const u64 xc = *reinterpret_cast<const u64*>(xrow + 8);
        acc[r][0] = ffma2(wih2[0][0], xa.x, acc[r][0]);
        acc[r][1] = ffma2(wih2[1][0], xa.x, acc[r][1]);
        acc[r][2] = ffma2(wih2[2][0], xa.x, acc[r][2]);
        acc[r][0] = ffma2(wih2[0][1], xa.y, acc[r][0]);
        acc[r][1] = ffma2(wih2[1][1], xa.y, acc[r][1]);
        acc[r][2] = ffma2(wih2[2][1], xa.y, acc[r][2]);
        acc[r][0] = ffma2(wih2[0][2], xb.x, acc[r][0]);
        acc[r][1] = ffma2(wih2[1][2], xb.x, acc[r][1]);
        acc[r][2] = ffma2(wih2[2][2], xb.x, acc[r][2]);
        acc[r][0] = ffma2(wih2[0][3], xb.y, acc[r][0]);
        acc[r][1] = ffma2(wih2[1][3], xb.y, acc[r][1]);
        acc[r][2] = ffma2(wih2[2][3], xb.y, acc[r][2]);
        acc[r][0] = ffma2(wih2[0][4], xc, acc[r][0]);
        acc[r][1] = ffma2(wih2[1][4], xc, acc[r][1]);
        acc[r][2] = ffma2(wih2[2][4], xc, acc[r][2]);
    }
}

__global__ void __launch_bounds__(NTHREADS, 4) lstm_r6_kernel(
    const float* __restrict__ x,      // [T, B, I]
    const float* __restrict__ h0,     // [B, H]
    const float* __restrict__ c0,     // [B, H]
    const float* __restrict__ Wih,    // [4H, I]
    const float* __restrict__ Whh,    // [4H, H]
    const float* __restrict__ bih,    // [4H]
    const float* __restrict__ bhh,    // [4H]
    float* __restrict__ out,
    long long out_size)
{
    const int lane = threadIdx.x & 31;
    const int w    = threadIdx.x >> 5;
    const int b0   = blockIdx.x * NB + 2 * w;

    __shared__ __align__(16) float sm[WARPS_PER_CTA][WREG_F];
    float* const hbuf = &sm[w][H_OFF];
    float* const gbuf = &sm[w][G_OFF];
    float* const xs   = &sm[w][X_OFF];

    // ---- weights: lane owns 3 consecutive padded gate-rows, all in ONE gate
    u64 wih2[3][5], whh2[3][10], bias2[3];
    const int gate = lane >> 3;                // rows 3L..3L+2, gate = L/8
    const float s_ = (gate == 2) ? 1.0f : 0.5f; // act = fma(tanh(s*z), s, 1-s)
    const float o_ = 1.0f - s_;
#pragma unroll
    for (int rr = 0; rr < 3; rr++) {
        const int jj  = 3 * lane + rr - gate * JPAD;
        const int row = gate * HSZ + jj;
        if (jj < HSZ) {
            const float* wr = Wih + row * ISZ;
#pragma unroll
            for (int k = 0; k < 5; k++)
                wih2[rr][k] = *reinterpret_cast<const u64*>(wr + 2 * k);
            const float* wr2 = Whh + row * HSZ;
#pragma unroll
            for (int k = 0; k < 10; k++)
                whh2[rr][k] = *reinterpret_cast<const u64*>(wr2 + 2 * k);
            bias2[rr] = pack2(bih[row] + bhh[row], 0.0f);
        } else {
#pragma unroll
            for (int k = 0; k < 5; k++)  wih2[rr][k] = 0ull;
#pragma unroll
            for (int k = 0; k < 10; k++) whh2[rr][k] = 0ull;
            bias2[rr] = 0ull;
        }
    }

    // ---- phase2 item mapping: 40 items (2 rows x 20 units) over 32 lanes
    const int it0_r = (lane < HSZ) ? 0 : 1;
    const int it0_j = (lane < HSZ) ? lane : lane - HSZ;
    const bool has1 = (lane < 8);              // item1: r=1, j=lane+12

    float c_a, c_b = 0.0f, hn_a = 0.0f, hn_b = 0.0f;
    c_a = c0[(size_t)(b0 + it0_r) * HSZ + it0_j];
    hbuf[it0_r * H_ROW + it0_j] = h0[(size_t)(b0 + it0_r) * HSZ + it0_j];
    if (has1) {
        c_b = c0[(size_t)(b0 + 1) * HSZ + lane + 12];
        hbuf[H_ROW + lane + 12] = h0[(size_t)(b0 + 1) * HSZ + lane + 12];
    }

    const float* xbase = x + (size_t)b0 * ISZ;
    const size_t x_step = (size_t)BATCH * ISZ;

    // stage xs buf0 = x[0]
    if (lane < 10) {
        const u64 v = *reinterpret_cast<const u64*>(xbase + 2 * lane);
        const int so = (lane < 5) ? 2 * lane : 12 + 2 * (lane - 5);
        *reinterpret_cast<u64*>(xs + so) = v;
    }
    __syncwarp();

    // initial acc = bias + xproj(x[0])
    u64 acc[2][3];
    xproj(acc, xs, wih2, bias2);

    float* op = out + (size_t)b0 * HSZ;
    const size_t o_step = (size_t)BATCH * HSZ;

    for (int t = 0; t < T_STEPS; t++) {
        const int cur = t & 1;

        // prefetch x[t+1] (LDG early; STS just before sync#1)
        u64 xpre = 0ull;
        if (lane < 10) {
            const float* xq = xbase + (size_t)((t + 1 < T_STEPS) ? t + 1 : t) * x_step;
            xpre = *reinterpret_cast<const u64*>(xq + 2 * lane);
        }

        // ---- h-projection (acc already holds bias + xproj(t)) ----
#pragma unroll
        for (int r = 0; r < 2; r++) {
            const float* hcur = hbuf + cur * HB_BUF + r * H_ROW;
#pragma unroll
            for (int k4 = 0; k4 < 5; k4++) {
                const ulonglong2 hv = *reinterpret_cast<const ulonglong2*>(hcur + 4 * k4);
                acc[r][0] = ffma2(whh2[0][2 * k4],     hv.x, acc[r][0]);
                acc[r][1] = ffma2(whh2[1][2 * k4],     hv.x, acc[r][1]);
                acc[r][2] = ffma2(whh2[2][2 * k4],     hv.x, acc[r][2]);
                acc[r][0] = ffma2(whh2[0][2 * k4 + 1], hv.y, acc[r][0]);
                acc[r][1] = ffma2(whh2[1][2 * k4 + 1], hv.y, acc[r][1]);
                acc[r][2] = ffma2(whh2[2][2 * k4 + 1], hv.y, acc[r][2]);
            }
        }

        // ---- activations + gate store (stride-3, conflict-free) ----
#pragma unroll
        for (int r = 0; r < 2; r++) {
            float lo, hi;
            unpack2(acc[r][0], lo, hi);
            const float v0 = fmaf(tanh_fast(s_ * (lo + hi)), s_, o_);
            unpack2(acc[r][1], lo, hi);
            const float v1 = fmaf(tanh_fast(s_ * (lo + hi)), s_, o_);
            unpack2(acc[r][2], lo, hi);
            const float v2 = fmaf(tanh_fast(s_ * (lo + hi)), s_, o_);
            float* gb = gbuf + r * G_ROW;
            gb[3 * lane + 0] = v0;
            gb[3 * lane + 1] = v1;
            gb[3 * lane + 2] = v2;
        }

        // stage x[t+1] into the other xs buffer
        if (lane < 10) {
            const int so = (cur ^ 1) * 24 + ((lane < 5) ? 2 * lane : 12 + 2 * (lane - 5));
            *reinterpret_cast<u64*>(xs + so) = xpre;
        }
        __syncwarp();   // gates + xs(t+1) visible

        // ---- x-projection for step t+1 into the now-dead accumulators:
        //      30 ffma2 overlapping the gate-LDS latency and phase2 chain ----
        xproj(acc, xs + (cur ^ 1) * 24, wih2, bias2);

        // ---- phase2: 40 items over 32 lanes ----
        {
            const float* gb0 = gbuf + it0_r * G_ROW;
            const float gi = gb0[it0_j];
            const float gf = gb0[JPAD + it0_j];
            const float gg = gb0[2 * JPAD + it0_j];
            const float go = gb0[3 * JPAD + it0_j];
            c_a  = fmaf(gf, c_a, gi * gg);
            hn_a = go * tanh_fast(c_a);
            hbuf[(cur ^ 1) * HB_BUF + it0_r * H_ROW + it0_j] = hn_a;
            op[it0_r * HSZ + it0_j] = hn_a;
            if (has1) {
                const float* gb1 = gbuf + G_ROW;
                const int j1 = lane + 12;
                const float gi1 = gb1[j1];
                const float gf1 = gb1[JPAD + j1];
                const float gg1 = gb1[2 * JPAD + j1];
                const float go1 = gb1[3 * JPAD + j1];
                c_b  = fmaf(gf1, c_b, gi1 * gg1);
                hn_b = go1 * tanh_fast(c_b);
                hbuf[(cur ^ 1) * HB_BUF + H_ROW + j1] = hn_b;
                op[HSZ + j1] = hn_b;
            }
        }
        __syncwarp();   // h(t) visible for step t+1

        op += o_step;
    }

    // ---- final h, c appended after outputs ----
    const long long base = (long long)T_STEPS * BATCH * HSZ;
    if (out_size >= base + 2LL * BATCH * HSZ) {
        out[base + (size_t)(b0 + it0_r) * HSZ + it0_j] = hn_a;
        out[base + (size_t)BATCH * HSZ + (size_t)(b0 + it0_r) * HSZ + it0_j] = c_a;
        if (has1) {
            out[base + (size_t)(b0 + 1) * HSZ + lane + 12] = hn_b;
            out[base + (size_t)BATCH * HSZ + (size_t)(b0 + 1) * HSZ + lane + 12] = c_b;
        }
    }
}

extern "C" void kernel_launch(void* const* d_in, const int* in_sizes, int n_in,
                              void* d_out, int out_size) {
    const float* x   = (const float*)d_in[0];
    const float* h0  = (const float*)d_in[1];
    const float* c0  = (const float*)d_in[2];
    const float* Wih = (const float*)d_in[3];
    const float* Whh = (const float*)d_in[4];
    const float* bih = (const float*)d_in[5];
    const float* bhh = (const float*)d_in[6];
    float* out = (float*)d_out;

    dim3 grid(BATCH / NB);     // 512 CTAs -> one resident wave at 4 CTA/SM
    dim3 block(NTHREADS);      // 128 threads
    lstm_r6_kernel<<<grid, block>>>(x, h0, c0, Wih, Whh, bih, bhh,
                                    out, (long long)out_size);
}

// round 7
// speedup vs baseline: 1.3239x; 1.3239x over previous
#include <cuda_runtime.h>

// LSTM T=512, B=4096, I=10, H=20.
// Thread = (unit j, gate-pair, 2 batch rows):
//   even lane: gates (i, g) -> computes i*g locally
//   odd  lane: gates (f, o) -> receives i*g via shfl_xor(1), owns c/h update
// NO gate smem exchange; ONE __syncthreads per step (h broadcast only).
// CTA = 160 threads = 8 batch rows; weights register-resident (60 regs);
// fma.rn.f32x2 packed math; tanh.approx. 512 CTAs -> one wave at 4 CTA/SM.

#define T_STEPS 512
#define BATCH   4096
#define ISZ     10
#define HSZ     20
#define ROWS_CTA 8
#define NTHREADS 160

typedef unsigned long long u64;

__device__ __forceinline__ u64 pack2(float x, float y) {
    u64 r; asm("mov.b64 %0, {%1,%2};" : "=l"(r) : "f"(x), "f"(y)); return r;
}
__device__ __forceinline__ void unpack2(u64 v, float& x, float& y) {
    asm("mov.b64 {%0,%1}, %2;" : "=f"(x), "=f"(y) : "l"(v));
}
__device__ __forceinline__ u64 ffma2(u64 a, u64 b, u64 c) {
    u64 r; asm("fma.rn.f32x2 %0, %1, %2, %3;" : "=l"(r) : "l"(a), "l"(b), "l"(c));
    return r;
}
__device__ __forceinline__ float tanh_fast(float x) {
    float y; asm("tanh.approx.f32 %0, %1;" : "=f"(y) : "f"(x)); return y;
}

// smem: h double buffer [2][8][20] + x staging [2][8][12]
#define HBUF_F (2 * ROWS_CTA * HSZ)        // 320
#define XS_F   (2 * ROWS_CTA * 12)         // 192

__global__ void __launch_bounds__(NTHREADS, 4) lstm_pair_kernel(
    const float* __restrict__ x,      // [T, B, I]
    const float* __restrict__ h0,     // [B, H]
    const float* __restrict__ c0,     // [B, H]
    const float* __restrict__ Wih,    // [4H, I]
    const float* __restrict__ Whh,    // [4H, H]
    const float* __restrict__ bih,    // [4H]
    const float* __restrict__ bhh,    // [4H]
    float* __restrict__ out,
    long long out_size)
{
    const int tid  = threadIdx.x;
    const int half = tid & 1;             // 0: (i,g)  1: (f,o)
    const int p    = tid >> 1;            // 0..79
    const int rg   = p / HSZ;             // 0..3: local row group
    const int j    = p % HSZ;             // hidden unit
    const int rA   = rg;                  // local rows rA, rB = rA+4
    const int rB   = rg + 4;
    const int bA   = blockIdx.x * ROWS_CTA + rA;   // global batch rows
    const int bB   = blockIdx.x * ROWS_CTA + rB;

    __shared__ __align__(16) float hbuf[HBUF_F];
    __shared__ __align__(16) float xs[XS_F];

    // gates: even -> (0:i, 2:g), odd -> (1:f, 3:o)
    const int g0 = half ? 1 : 0;
    const int g1 = half ? 3 : 2;
    const float s1 = half ? 0.5f : 1.0f;  // gate g is tanh (s=1); others sigmoid
    const float o1 = 1.0f - s1;

    // ---- register-resident weights for my two gate-rows ----
    u64 wx[2][5], wh[2][10];
    u64 bias2[2];
    {
        const int rows[2] = {g0 * HSZ + j, g1 * HSZ + j};
#pragma unroll
        for (int q = 0; q < 2; q++) {
            const float* wr = Wih + rows[q] * ISZ;
#pragma unroll
            for (int k = 0; k < 5; k++)
                wx[q][k] = *reinterpret_cast<const u64*>(wr + 2 * k);
            const float* wr2 = Whh + rows[q] * HSZ;
#pragma unroll
            for (int k = 0; k < 10; k++)
                wh[q][k] = *reinterpret_cast<const u64*>(wr2 + 2 * k);
            bias2[q] = pack2(bih[rows[q]] + bhh[rows[q]], 0.0f);
        }
    }

    // ---- init state ----
    float cA = c0[(size_t)bA * HSZ + j];     // meaningful on odd lanes
    float cB = c0[(size_t)bB * HSZ + j];
    float hA = 0.0f, hB = 0.0f;
    if (half) {                               // odd lanes seed h buffer
        hbuf[rA * HSZ + j] = h0[(size_t)bA * HSZ + j];
        hbuf[rB * HSZ + j] = h0[(size_t)bB * HSZ + j];
    }

    // stage x[0]: CTA's 8 rows are 320B contiguous at x + blk*8*ISZ
    const float* xcta = x + (size_t)blockIdx.x * ROWS_CTA * ISZ;
    const size_t x_step = (size_t)BATCH * ISZ;
    if (tid < 40) {
        const u64 v = *reinterpret_cast<const u64*>(xcta + 2 * tid);
        xs[(tid / 5) * 12 + (tid % 5) * 2]     = __uint_as_float((unsigned)(v & 0xFFFFFFFFu));
        xs[(tid / 5) * 12 + (tid % 5) * 2 + 1] = __uint_as_float((unsigned)(v >> 32));
    }
    __syncthreads();

    float* opA = out + (size_t)bA * HSZ + j;
    float* opB = out + (size_t)bB * HSZ + j;
    const size_t o_step = (size_t)BATCH * HSZ;

    for (int t = 0; t < T_STEPS; t++) {
        const int cur = t & 1;

        // prefetch x[t+1] (consumed after this step's barrier)
        u64 xpre = 0ull;
        if (tid < 40) {
            const float* xq = xcta + (size_t)((t + 1 < T_STEPS) ? t + 1 : t) * x_step;
            xpre = *reinterpret_cast<const u64*>(xq + 2 * tid);
        }

        // ---- projections: acc[row][gate q] ----
        u64 aA0 = bias2[0], aA1 = bias2[1], aB0 = bias2[0], aB1 = bias2[1];

        // x projection from staged smem
        {
            const float* xrA = xs + cur * (ROWS_CTA * 12) + rA * 12;
            const float* xrB = xs + cur * (ROWS_CTA * 12) + rB * 12;
            const ulonglong2 a01 = *reinterpret_cast<const ulonglong2*>(xrA);
            const u64        a2  = *reinterpret_cast<const u64*>(xrA + 8);
            const ulonglong2 b01 = *reinterpret_cast<const ulonglong2*>(xrB);
            const u64        b2  = *reinterpret_cast<const u64*>(xrB + 8);
            // k=0..4 pairs: a01.x/a01.y cover k=0,1; need k=2,3 too
            const ulonglong2 a23 = *reinterpret_cast<const ulonglong2*>(xrA + 4);
            const ulonglong2 b23 = *reinterpret_cast<const ulonglong2*>(xrB + 4);
            aA0 = ffma2(wx[0][0], a01.x, aA0);  aA1 = ffma2(wx[1][0], a01.x, aA1);
            aA0 = ffma2(wx[0][1], a01.y, aA0);  aA1 = ffma2(wx[1][1], a01.y, aA1);
            aA0 = ffma2(wx[0][2], a23.x, aA0);  aA1 = ffma2(wx[1][2], a23.x, aA1);
            aA0 = ffma2(wx[0][3], a23.y, aA0);  aA1 = ffma2(wx[1][3], a23.y, aA1);
            aA0 = ffma2(wx[0][4], a2,    aA0);  aA1 = ffma2(wx[1][4], a2,    aA1);
            aB0 = ffma2(wx[0][0], b01.x, aB0);  aB1 = ffma2(wx[1][0], b01.x, aB1);
            aB0 = ffma2(wx[0][1], b01.y, aB0);  aB1 = ffma2(wx[1][1], b01.y, aB1);
            aB0 = ffma2(wx[0][2], b23.x, aB0);  aB1 = ffma2(wx[1][2], b23.x, aB1);
            aB0 = ffma2(wx[0][3], b23.y, aB0);  aB1 = ffma2(wx[1][3], b23.y, aB1);
            aB0 = ffma2(wx[0][4], b2,    aB0);  aB1 = ffma2(wx[1][4], b2,    aB1);
        }

        // h projection (rows are 80B = 5x16B chunks, broadcast LDS.128)
        {
            const float* hA_ = hbuf + cur * (ROWS_CTA * HSZ) + rA * HSZ;
            const float* hB_ = hbuf + cur * (ROWS_CTA * HSZ) + rB * HSZ;
#pragma unroll
            for (int k4 = 0; k4 < 5; k4++) {
                const ulonglong2 va = *reinterpret_cast<const ulonglong2*>(hA_ + 4 * k4);
                const ulonglong2 vb = *reinterpret_cast<const ulonglong2*>(hB_ + 4 * k4);
                aA0 = ffma2(wh[0][2 * k4],     va.x, aA0);
                aA1 = ffma2(wh[1][2 * k4],     va.x, aA1);
                aA0 = ffma2(wh[0][2 * k4 + 1], va.y, aA0);
                aA1 = ffma2(wh[1][2 * k4 + 1], va.y, aA1);
                aB0 = ffma2(wh[0][2 * k4],     vb.x, aB0);
                aB1 = ffma2(wh[1][2 * k4],     vb.x, aB1);
                aB0 = ffma2(wh[0][2 * k4 + 1], vb.y, aB0);
                aB1 = ffma2(wh[1][2 * k4 + 1], vb.y, aB1);
            }
        }

        // ---- activations ----
        float lo, hi;
        unpack2(aA0, lo, hi);
        const float vA0 = fmaf(tanh_fast(0.5f * (lo + hi)), 0.5f, 0.5f); // i | f
        unpack2(aA1, lo, hi);
        const float vA1 = fmaf(tanh_fast(s1 * (lo + hi)), s1, o1);       // g | o
        unpack2(aB0, lo, hi);
        const float vB0 = fmaf(tanh_fast(0.5f * (lo + hi)), 0.5f, 0.5f);
        unpack2(aB1, lo, hi);
        const float vB1 = fmaf(tanh_fast(s1 * (lo + hi)), s1, o1);

        // even lane: p = i*g ; hand to odd lane
        const float pA = vA0 * vA1;
        const float pB = vB0 * vB1;
        const float qA = __shfl_xor_sync(0xFFFFFFFFu, pA, 1);
        const float qB = __shfl_xor_sync(0xFFFFFFFFu, pB, 1);

        if (half) {   // odd lane: vA0=f, vA1=o
            cA = fmaf(vA0, cA, qA);
            hA = vA1 * tanh_fast(cA);
            cB = fmaf(vB0, cB, qB);
            hB = vB1 * tanh_fast(cB);
            float* hnxt = hbuf + (cur ^ 1) * (ROWS_CTA * HSZ);
            hnxt[rA * HSZ + j] = hA;
            hnxt[rB * HSZ + j] = hB;
            opA[0] = hA;
            opB[0] = hB;
        }

        // stage x[t+1] into the other buffer
        if (tid < 40) {
            float* xd = xs + (cur ^ 1) * (ROWS_CTA * 12) + (tid / 5) * 12 + (tid % 5) * 2;
            xd[0] = __uint_as_float((unsigned)(xpre & 0xFFFFFFFFu));
            xd[1] = __uint_as_float((unsigned)(xpre >> 32));
        }

        __syncthreads();   // h(t), xs(t+1) visible

        opA += o_step;
        opB += o_step;
    }

    // ---- final h, c appended after outputs (held by odd lanes) ----
    const long long base = (long long)T_STEPS * BATCH * HSZ;
    if (half && out_size >= base + 2LL * BATCH * HSZ) {
        out[base + (size_t)bA * HSZ + j] = hA;
        out[base + (size_t)bB * HSZ + j] = hB;
        out[base + (size_t)BATCH * HSZ + (size_t)bA * HSZ + j] = cA;
        out[base + (size_t)BATCH * HSZ + (size_t)bB * HSZ + j] = cB;
    }
}

extern "C" void kernel_launch(void* const* d_in, const int* in_sizes, int n_in,
                              void* d_out, int out_size) {
    const float* x   = (const float*)d_in[0];
    const float* h0  = (const float*)d_in[1];
    const float* c0  = (const float*)d_in[2];
    const float* Wih = (const float*)d_in[3];
    const float* Whh = (const float*)d_in[4];
    const float* bih = (const float*)d_in[5];
    const float* bhh = (const float*)d_in[6];
    float* out = (float*)d_out;

    dim3 grid(BATCH / ROWS_CTA);   // 512 CTAs -> one resident wave
    dim3 block(NTHREADS);          // 160 threads
    lstm_pair_kernel<<<grid, block>>>(x, h0, c0, Wih, Whh, bih, bhh,
                                      out, (long long)out_size);
}

// round 8
// speedup vs baseline: 1.3559x; 1.0241x over previous
#include <cuda_runtime.h>

// LSTM T=512, B=4096, I=10, H=20.
// Thread = (unit j, gate-pair, 2 batch rows). Even lane: (i,g); odd: (f,o).
// R8: fully balanced step tail -- 3 shfls route gates so EVERY lane updates
// exactly one row's (c,h): odd lane owns row A, even lane owns row B.
// Loop body is branch-free; x staging spread 8 threads/warp (tid%4==3).
// Weights register-resident; fma.rn.f32x2; tanh.approx; one barrier/step.

#define T_STEPS 512
#define BATCH   4096
#define ISZ     10
#define HSZ     20
#define ROWS_CTA 8
#define NTHREADS 160

typedef unsigned long long u64;

__device__ __forceinline__ u64 pack2(float x, float y) {
    u64 r; asm("mov.b64 %0, {%1,%2};" : "=l"(r) : "f"(x), "f"(y)); return r;
}
__device__ __forceinline__ void unpack2(u64 v, float& x, float& y) {
    asm("mov.b64 {%0,%1}, %2;" : "=f"(x), "=f"(y) : "l"(v));
}
__device__ __forceinline__ u64 ffma2(u64 a, u64 b, u64 c) {
    u64 r; asm("fma.rn.f32x2 %0, %1, %2, %3;" : "=l"(r) : "l"(a), "l"(b), "l"(c));
    return r;
}
__device__ __forceinline__ float tanh_fast(float x) {
    float y; asm("tanh.approx.f32 %0, %1;" : "=f"(y) : "f"(x)); return y;
}

#define HBUF_F (2 * ROWS_CTA * HSZ)        // 320 floats
#define XS_ROW 12
#define XS_BUF (ROWS_CTA * XS_ROW)         // 96
#define XS_F   (2 * XS_BUF)                // 192

__global__ void __launch_bounds__(NTHREADS, 4) lstm_r8_kernel(
    const float* __restrict__ x,      // [T, B, I]
    const float* __restrict__ h0,     // [B, H]
    const float* __restrict__ c0,     // [B, H]
    const float* __restrict__ Wih,    // [4H, I]
    const float* __restrict__ Whh,    // [4H, H]
    const float* __restrict__ bih,    // [4H]
    const float* __restrict__ bhh,    // [4H]
    float* __restrict__ out,
    long long out_size)
{
    const int tid  = threadIdx.x;
    const int half = tid & 1;             // 0: (i,g)  1: (f,o)
    const int p    = tid >> 1;            // 0..79
    const int rg   = p / HSZ;             // 0..3
    const int j    = p % HSZ;
    const int rA   = rg;
    const int rB   = rg + 4;
    const int bA   = blockIdx.x * ROWS_CTA + rA;
    const int bB   = blockIdx.x * ROWS_CTA + rB;

    __shared__ __align__(16) float hbuf[HBUF_F];
    __shared__ __align__(16) float xs[XS_F];

    const int g0 = half ? 1 : 0;          // f | i   (sigmoid)
    const int g1 = half ? 3 : 2;          // o | g   (sigmoid | tanh)
    const float s1 = half ? 0.5f : 1.0f;
    const float o1 = 1.0f - s1;

    // ---- register-resident weights (2 gate-rows) ----
    u64 wx[2][5], wh[2][10], bias2[2];
    {
        const int rows[2] = {g0 * HSZ + j, g1 * HSZ + j};
#pragma unroll
        for (int q = 0; q < 2; q++) {
            const float* wr = Wih + rows[q] * ISZ;
#pragma unroll
            for (int k = 0; k < 5; k++)
                wx[q][k] = *reinterpret_cast<const u64*>(wr + 2 * k);
            const float* wr2 = Whh + rows[q] * HSZ;
#pragma unroll
            for (int k = 0; k < 10; k++)
                wh[q][k] = *reinterpret_cast<const u64*>(wr2 + 2 * k);
            bias2[q] = pack2(bih[rows[q]] + bhh[rows[q]], 0.0f);
        }
    }

    // ---- my owned row for the state update: odd -> row A, even -> row B ----
    const int  myrow = half ? rA : rB;
    const int  bmy   = half ? bA : bB;

    float c_ = c0[(size_t)bmy * HSZ + j];
    float h_ = 0.0f;
    hbuf[myrow * HSZ + j] = h0[(size_t)bmy * HSZ + j];   // all 160 units covered

    // ---- x staging: 40 slots spread 8 per warp (tid%4==3) ----
    const bool stager = ((tid & 3) == 3);
    const int  slot   = tid >> 2;             // 0..39 on stagers
    const int  srow   = slot / 5;
    const int  schk   = slot % 5;
    const float* xcta = x + (size_t)blockIdx.x * ROWS_CTA * ISZ;
    const size_t x_step = (size_t)BATCH * ISZ;

    if (stager) {
        const u64 v = *reinterpret_cast<const u64*>(xcta + srow * ISZ + schk * 2);
        *reinterpret_cast<u64*>(xs + srow * XS_ROW + schk * 2) = v;
    }
    __syncthreads();

    float* opmy = out + (size_t)bmy * HSZ + j;
    const size_t o_step = (size_t)BATCH * HSZ;

    for (int t = 0; t < T_STEPS; t++) {
        const int cur = t & 1;

        // prefetch x[t+1]
        u64 xpre = 0ull;
        if (stager) {
            const float* xq = xcta + (size_t)((t + 1 < T_STEPS) ? t + 1 : t) * x_step;
            xpre = *reinterpret_cast<const u64*>(xq + srow * ISZ + schk * 2);
        }

        // ---- projections ----
        u64 aA0 = bias2[0], aA1 = bias2[1], aB0 = bias2[0], aB1 = bias2[1];
        {
            const float* xrA = xs + cur * XS_BUF + rA * XS_ROW;
            const float* xrB = xs + cur * XS_BUF + rB * XS_ROW;
            const ulonglong2 a01 = *reinterpret_cast<const ulonglong2*>(xrA);
            const ulonglong2 a23 = *reinterpret_cast<const ulonglong2*>(xrA + 4);
            const u64        a4  = *reinterpret_cast<const u64*>(xrA + 8);
            const ulonglong2 b01 = *reinterpret_cast<const ulonglong2*>(xrB);
            const ulonglong2 b23 = *reinterpret_cast<const ulonglong2*>(xrB + 4);
            const u64        b4  = *reinterpret_cast<const u64*>(xrB + 8);
            aA0 = ffma2(wx[0][0], a01.x, aA0);  aA1 = ffma2(wx[1][0], a01.x, aA1);
            aA0 = ffma2(wx[0][1], a01.y, aA0);  aA1 = ffma2(wx[1][1], a01.y, aA1);
            aA0 = ffma2(wx[0][2], a23.x, aA0);  aA1 = ffma2(wx[1][2], a23.x, aA1);
            aA0 = ffma2(wx[0][3], a23.y, aA0);  aA1 = ffma2(wx[1][3], a23.y, aA1);
            aA0 = ffma2(wx[0][4], a4,    aA0);  aA1 = ffma2(wx[1][4], a4,    aA1);
            aB0 = ffma2(wx[0][0], b01.x, aB0);  aB1 = ffma2(wx[1][0], b01.x, aB1);
            aB0 = ffma2(wx[0][1], b01.y, aB0);  aB1 = ffma2(wx[1][1], b01.y, aB1);
            aB0 = ffma2(wx[0][2], b23.x, aB0);  aB1 = ffma2(wx[1][2], b23.x, aB1);
            aB0 = ffma2(wx[0][3], b23.y, aB0);  aB1 = ffma2(wx[1][3], b23.y, aB1);
            aB0 = ffma2(wx[0][4], b4,    aB0);  aB1 = ffma2(wx[1][4], b4,    aB1);
        }
        {
            const float* hA_ = hbuf + cur * (ROWS_CTA * HSZ) + rA * HSZ;
            const float* hB_ = hbuf + cur * (ROWS_CTA * HSZ) + rB * HSZ;
#pragma unroll
            for (int k4 = 0; k4 < 5; k4++) {
                const ulonglong2 va = *reinterpret_cast<const ulonglong2*>(hA_ + 4 * k4);
                const ulonglong2 vb = *reinterpret_cast<const ulonglong2*>(hB_ + 4 * k4);
                aA0 = ffma2(wh[0][2 * k4],     va.x, aA0);
                aA1 = ffma2(wh[1][2 * k4],     va.x, aA1);
                aA0 = ffma2(wh[0][2 * k4 + 1], va.y, aA0);
                aA1 = ffma2(wh[1][2 * k4 + 1], va.y, aA1);
                aB0 = ffma2(wh[0][2 * k4],     vb.x, aB0);
                aB1 = ffma2(wh[1][2 * k4],     vb.x, aB1);
                aB0 = ffma2(wh[0][2 * k4 + 1], vb.y, aB0);
                aB1 = ffma2(wh[1][2 * k4 + 1], vb.y, aB1);
            }
        }

        // ---- activations ----
        float lo, hi;
        unpack2(aA0, lo, hi);
        const float vA0 = fmaf(tanh_fast(0.5f * (lo + hi)), 0.5f, 0.5f); // i|f (A)
        unpack2(aA1, lo, hi);
        const float vA1 = fmaf(tanh_fast(s1 * (lo + hi)), s1, o1);       // g|o (A)
        unpack2(aB0, lo, hi);
        const float vB0 = fmaf(tanh_fast(0.5f * (lo + hi)), 0.5f, 0.5f); // i|f (B)
        unpack2(aB1, lo, hi);
        const float vB1 = fmaf(tanh_fast(s1 * (lo + hi)), s1, o1);       // g|o (B)

        // even lane: tA = iA*gA (pA), tB = iB*gB (pB). odd lane values unused/peer.
        const float tA = vA0 * vA1;
        const float tB = vB0 * vB1;

        // route: odd gets pA; even gets fB, oB
        const float rAp = __shfl_xor_sync(0xFFFFFFFFu, tA,  1); // odd: pA
        const float rB0 = __shfl_xor_sync(0xFFFFFFFFu, vB0, 1); // even: fB
        const float rB1 = __shfl_xor_sync(0xFFFFFFFFu, vB1, 1); // even: oB

        // ---- uniform per-lane update of ONE row ----
        const float f_eff = half ? vA0 : rB0;
        const float p_eff = half ? rAp : tB;
        const float o_eff = half ? vA1 : rB1;
        c_ = fmaf(f_eff, c_, p_eff);
        h_ = o_eff * tanh_fast(c_);
        hbuf[(cur ^ 1) * (ROWS_CTA * HSZ) + myrow * HSZ + j] = h_;
        opmy[0] = h_;

        // stage x[t+1]
        if (stager)
            *reinterpret_cast<u64*>(xs + (cur ^ 1) * XS_BUF + srow * XS_ROW + schk * 2) = xpre;

        __syncthreads();
        opmy += o_step;
    }

    // ---- final h, c ----
    const long long base = (long long)T_STEPS * BATCH * HSZ;
    if (out_size >= base + 2LL * BATCH * HSZ) {
        out[base + (size_t)bmy * HSZ + j] = h_;
        out[base + (size_t)BATCH * HSZ + (size_t)bmy * HSZ + j] = c_;
    }
}

extern "C" void kernel_launch(void* const* d_in, const int* in_sizes, int n_in,
                              void* d_out, int out_size) {
    const float* x   = (const float*)d_in[0];
    const float* h0  = (const float*)d_in[1];
    const float* c0  = (const float*)d_in[2];
    const float* Wih = (const float*)d_in[3];
    const float* Whh = (const float*)d_in[4];
    const float* bih = (const float*)d_in[5];
    const float* bhh = (const float*)d_in[6];
    float* out = (float*)d_out;

    dim3 grid(BATCH / ROWS_CTA);   // 512 CTAs -> one resident wave at 4 CTA/SM
    dim3 block(NTHREADS);          // 160 threads
    lstm_r8_kernel<<<grid, block>>>(x, h0, c0, Wih, Whh, bih, bhh,
                                    out, (long long)out_size);
}